// round 11
// baseline (speedup 1.0000x reference)
#include <cuda_runtime.h>
#include <cuda_bf16.h>
#include <cstdint>

#define N_NODES 50000
#define DEG     32
#define DFEAT   128
#define DIN     256
#define DOUT    256

#define BM 32
#define XLD 264          // bf16 row stride for xs (pad 8)

// smem: xs hi + lo
#define XS_HI_OFF 0u
#define XS_LO_OFF (BM * XLD * 2u)            // 16896
#define SMEM_BYTES (2u * BM * XLD * 2u)      // 33792

// W in fragment order: [ksg(16)][nblk(32)][lane(32)] -> uint4
//   .x/.y = hi bf16x2 (k low/high half of ksg) ; .z/.w = lo bf16x2
__device__ uint4 g_wfrag[16 * 32 * 32];      // 256 KB

__device__ __forceinline__ void bf16x2_split(float x, float y,
                                             uint32_t& hi, uint32_t& lo) {
    __nv_bfloat162 h = __float22bfloat162_rn(make_float2(x, y));
    float2 hf = __bfloat1622float2(h);
    __nv_bfloat162 l = __float22bfloat162_rn(make_float2(x - hf.x, y - hf.y));
    hi = *reinterpret_cast<uint32_t*>(&h);
    lo = *reinterpret_cast<uint32_t*>(&l);
}

__device__ __forceinline__ void mma_bf16(float* d, const uint32_t* a,
                                         uint32_t b0, uint32_t b1) {
    asm volatile(
        "mma.sync.aligned.m16n8k16.row.col.f32.bf16.bf16.f32 "
        "{%0,%1,%2,%3}, {%4,%5,%6,%7}, {%8,%9}, {%0,%1,%2,%3};"
        : "+f"(d[0]), "+f"(d[1]), "+f"(d[2]), "+f"(d[3])
        : "r"(a[0]), "r"(a[1]), "r"(a[2]), "r"(a[3]),
          "r"(b0), "r"(b1));
}

// ------------- prologue: split W into fragment-ordered uint4 ---------------
__global__ void wsplit_kernel(const float* __restrict__ W) {
    const int idx = blockIdx.x * blockDim.x + threadIdx.x;   // 16384
    const int lane = idx & 31;
    const int nblk = (idx >> 5) & 31;
    const int ksg  = idx >> 10;            // 0..15
    const int g = lane >> 2, t = lane & 3;
    const int n  = nblk * 8 + g;
    const int k0 = ksg * 16 + 2 * t;
    const int k1 = k0 + 8;

    uint4 v;
    bf16x2_split(W[k0 * DOUT + n], W[(k0 + 1) * DOUT + n], v.x, v.z);
    bf16x2_split(W[k1 * DOUT + n], W[(k1 + 1) * DOUT + n], v.y, v.w);
    g_wfrag[idx] = v;
}

// ------------------------------ fused kernel -------------------------------
__global__ __launch_bounds__(256, 4)
void sage_fused_kernel(const float* __restrict__ features,
                       const int* __restrict__ edges,
                       float* __restrict__ out)
{
    extern __shared__ char sm[];
    uint32_t* xs_hi = reinterpret_cast<uint32_t*>(sm + XS_HI_OFF);
    uint32_t* xs_lo = reinterpret_cast<uint32_t*>(sm + XS_LO_OFF);

    const int tid  = threadIdx.x;
    const int lane = tid & 31;
    const int wid  = tid >> 5;            // 0..7
    const int node0 = blockIdx.x * BM;

    // ---------------- Phase 1: gather + mean + split to bf16 smem ----------
    // 8 warps x 4 nodes each
    #pragma unroll
    for (int s = 0; s < BM / 8; s++) {
        const int m = wid * (BM / 8) + s;
        const int node = node0 + m;
        const int wbase = m * (XLD / 2) + lane * 2;
        if (node < N_NODES) {
            const int my_e = edges[node * DEG + lane];
            const float4 self = *reinterpret_cast<const float4*>(
                features + (long long)node * DFEAT + lane * 4);

            float4 acc = make_float4(0.f, 0.f, 0.f, 0.f);
            #pragma unroll
            for (int j = 0; j < DEG; j++) {
                const int idx = __shfl_sync(0xffffffffu, my_e, j);
                const float4 v = *reinterpret_cast<const float4*>(
                    features + (long long)idx * DFEAT + lane * 4);
                acc.x += v.x; acc.y += v.y; acc.z += v.z; acc.w += v.w;
            }
            const float inv = 1.0f / (float)DEG;
            acc.x *= inv; acc.y *= inv; acc.z *= inv; acc.w *= inv;

            uint32_t h0, l0, h1, l1;
            bf16x2_split(self.x, self.y, h0, l0);
            bf16x2_split(self.z, self.w, h1, l1);
            xs_hi[wbase]     = h0;  xs_hi[wbase + 1] = h1;
            xs_lo[wbase]     = l0;  xs_lo[wbase + 1] = l1;

            bf16x2_split(acc.x, acc.y, h0, l0);
            bf16x2_split(acc.z, acc.w, h1, l1);
            xs_hi[wbase + 64] = h0; xs_hi[wbase + 65] = h1;
            xs_lo[wbase + 64] = l0; xs_lo[wbase + 65] = l1;
        } else {
            xs_hi[wbase] = 0u;      xs_hi[wbase + 1] = 0u;
            xs_lo[wbase] = 0u;      xs_lo[wbase + 1] = 0u;
            xs_hi[wbase + 64] = 0u; xs_hi[wbase + 65] = 0u;
            xs_lo[wbase + 64] = 0u; xs_lo[wbase + 65] = 0u;
        }
    }
    __syncthreads();

    // ---------------- Phase 2: bf16x3 GEMM, B direct from L2 ---------------
    // 8 warps, each owns M=32 x 32 N-cols (mt=2, nt=4); one reader per B frag.
    // Loop restructured (bw once per ksg, mt sequential) to fit 64 regs/thread.
    const int g  = lane >> 2;
    const int t  = lane & 3;
    const int n_base = wid * 32;

    float acc[2][4][4];
    #pragma unroll
    for (int mt = 0; mt < 2; mt++)
        #pragma unroll
        for (int nt = 0; nt < 4; nt++)
            #pragma unroll
            for (int r = 0; r < 4; r++)
                acc[mt][nt][r] = 0.f;

    // nblk = wid*4 + nt
    const uint4* wbase_p = g_wfrag + (wid * 4) * 32 + lane;

    #pragma unroll 1
    for (int ksg = 0; ksg < 16; ksg++) {
        // B fragments for this warp's 4 n-blocks
        uint4 bw[4];
        #pragma unroll
        for (int q = 0; q < 4; q++)
            bw[q] = wbase_p[(ksg * 32 + q) * 32];

        // mt sequential to shrink live A-frag registers
        #pragma unroll
        for (int mt = 0; mt < 2; mt++) {
            const int r0 = mt * 16 + g;
            const int i00 = r0 * (XLD / 2) + ksg * 8 + t;
            const int i01 = (r0 + 8) * (XLD / 2) + ksg * 8 + t;
            uint32_t ah[4], al[4];
            ah[0] = xs_hi[i00];     al[0] = xs_lo[i00];
            ah[1] = xs_hi[i01];     al[1] = xs_lo[i01];
            ah[2] = xs_hi[i00 + 4]; al[2] = xs_lo[i00 + 4];
            ah[3] = xs_hi[i01 + 4]; al[3] = xs_lo[i01 + 4];

            #pragma unroll
            for (int nt = 0; nt < 4; nt++) {
                mma_bf16(acc[mt][nt], ah, bw[nt].x, bw[nt].y);  // Ah*Bh
                mma_bf16(acc[mt][nt], al, bw[nt].x, bw[nt].y);  // Al*Bh
                mma_bf16(acc[mt][nt], ah, bw[nt].z, bw[nt].w);  // Ah*Bl
            }
        }
    }

    // ---------------- Phase 3: ReLU + store from registers -----------------
    #pragma unroll
    for (int mt = 0; mt < 2; mt++) {
        const int r0 = node0 + mt * 16 + g;
        #pragma unroll
        for (int nt = 0; nt < 4; nt++) {
            const int c0 = n_base + nt * 8 + t * 2;
            if (r0 < N_NODES) {
                float2 v0 = make_float2(fmaxf(acc[mt][nt][0], 0.f),
                                        fmaxf(acc[mt][nt][1], 0.f));
                *reinterpret_cast<float2*>(out + (long long)r0 * DOUT + c0) = v0;
            }
            if (r0 + 8 < N_NODES) {
                float2 v1 = make_float2(fmaxf(acc[mt][nt][2], 0.f),
                                        fmaxf(acc[mt][nt][3], 0.f));
                *reinterpret_cast<float2*>(out + (long long)(r0 + 8) * DOUT + c0) = v1;
            }
        }
    }
}

extern "C" void kernel_launch(void* const* d_in, const int* in_sizes, int n_in,
                              void* d_out, int out_size)
{
    const float* features = (const float*)d_in[0];
    const int*   edges    = (const int*)d_in[1];
    const float* kernel   = (const float*)d_in[2];
    float*       out      = (float*)d_out;
    (void)in_sizes; (void)n_in; (void)out_size;

    static bool attr_set = false;
    if (!attr_set) {
        cudaFuncSetAttribute(sage_fused_kernel,
                             cudaFuncAttributeMaxDynamicSharedMemorySize, SMEM_BYTES);
        attr_set = true;
    }

    wsplit_kernel<<<64, 256>>>(kernel);
    const int grid = (N_NODES + BM - 1) / BM;   // 1563
    sage_fused_kernel<<<grid, 256, SMEM_BYTES>>>(features, edges, out);
}

// round 12
// speedup vs baseline: 1.9301x; 1.9301x over previous
#include <cuda_runtime.h>
#include <cuda_bf16.h>
#include <cstdint>

#define N_NODES 50000
#define DEG     32
#define DFEAT   128
#define DIN     256
#define DOUT    256

#define BM 32
#define XLD 264          // bf16 row stride for xs (pad 8)

// smem: xs hi + lo
#define XS_HI_OFF 0u
#define XS_LO_OFF (BM * XLD * 2u)            // 16896
#define SMEM_BYTES (2u * BM * XLD * 2u)      // 33792

// W in fragment order: [ksg(16)][nblk(32)][lane(32)] -> uint4
__device__ uint4 g_wfrag[16 * 32 * 32];      // 256 KB

// bf16 copy of features, packed 2 cols/word: [node][64] uint32
__device__ uint32_t g_fh[N_NODES * (DFEAT / 2)];   // 12.8 MB

__device__ __forceinline__ void bf16x2_split(float x, float y,
                                             uint32_t& hi, uint32_t& lo) {
    __nv_bfloat162 h = __float22bfloat162_rn(make_float2(x, y));
    float2 hf = __bfloat1622float2(h);
    __nv_bfloat162 l = __float22bfloat162_rn(make_float2(x - hf.x, y - hf.y));
    hi = *reinterpret_cast<uint32_t*>(&h);
    lo = *reinterpret_cast<uint32_t*>(&l);
}

__device__ __forceinline__ void mma_bf16(float* d, const uint32_t* a,
                                         uint32_t b0, uint32_t b1) {
    asm volatile(
        "mma.sync.aligned.m16n8k16.row.col.f32.bf16.bf16.f32 "
        "{%0,%1,%2,%3}, {%4,%5,%6,%7}, {%8,%9}, {%0,%1,%2,%3};"
        : "+f"(d[0]), "+f"(d[1]), "+f"(d[2]), "+f"(d[3])
        : "r"(a[0]), "r"(a[1]), "r"(a[2]), "r"(a[3]),
          "r"(b0), "r"(b1));
}

// exact bf16(packed low/high) -> fp32
__device__ __forceinline__ float bf_lo(uint32_t w) { return __uint_as_float(w << 16); }
__device__ __forceinline__ float bf_hi(uint32_t w) { return __uint_as_float(w & 0xFFFF0000u); }

// ------------- prologue A: features -> packed bf16 table -------------------
__global__ void f2bf_kernel(const float* __restrict__ F) {
    const int idx = blockIdx.x * blockDim.x + threadIdx.x;   // word index
    if (idx < N_NODES * (DFEAT / 2)) {
        const float2 v = *reinterpret_cast<const float2*>(F + idx * 2);
        __nv_bfloat162 p = __float22bfloat162_rn(v);
        g_fh[idx] = *reinterpret_cast<uint32_t*>(&p);
    }
}

// ------------- prologue B: split W into fragment-ordered uint4 -------------
__global__ void wsplit_kernel(const float* __restrict__ W) {
    const int idx = blockIdx.x * blockDim.x + threadIdx.x;   // 16384
    const int lane = idx & 31;
    const int nblk = (idx >> 5) & 31;
    const int ksg  = idx >> 10;            // 0..15
    const int g = lane >> 2, t = lane & 3;
    const int n  = nblk * 8 + g;
    const int k0 = ksg * 16 + 2 * t;
    const int k1 = k0 + 8;

    uint4 v;
    bf16x2_split(W[k0 * DOUT + n], W[(k0 + 1) * DOUT + n], v.x, v.z);
    bf16x2_split(W[k1 * DOUT + n], W[(k1 + 1) * DOUT + n], v.y, v.w);
    g_wfrag[idx] = v;
}

// ------------------------------ fused kernel -------------------------------
__global__ __launch_bounds__(256, 3)
void sage_fused_kernel(const float* __restrict__ features,
                       const int* __restrict__ edges,
                       float* __restrict__ out)
{
    extern __shared__ char sm[];
    uint32_t* xs_hi = reinterpret_cast<uint32_t*>(sm + XS_HI_OFF);
    uint32_t* xs_lo = reinterpret_cast<uint32_t*>(sm + XS_LO_OFF);

    const int tid  = threadIdx.x;
    const int lane = tid & 31;
    const int wid  = tid >> 5;            // 0..7
    const int node0 = blockIdx.x * BM;

    // ---------------- Phase 1: gather (bf16 table) + mean + split ----------
    // 8 warps x 4 nodes each; lane covers feature cols [4*lane, 4*lane+4)
    #pragma unroll
    for (int s = 0; s < BM / 8; s++) {
        const int m = wid * (BM / 8) + s;
        const int node = node0 + m;
        const int wbase = m * (XLD / 2) + lane * 2;
        if (node < N_NODES) {
            const int my_e = edges[node * DEG + lane];
            const float4 self = *reinterpret_cast<const float4*>(
                features + (long long)node * DFEAT + lane * 4);

            float4 acc = make_float4(0.f, 0.f, 0.f, 0.f);
            #pragma unroll
            for (int j = 0; j < DEG; j++) {
                const int idx = __shfl_sync(0xffffffffu, my_e, j);
                const uint2 w = *reinterpret_cast<const uint2*>(
                    g_fh + idx * (DFEAT / 2) + lane * 2);
                acc.x += bf_lo(w.x); acc.y += bf_hi(w.x);
                acc.z += bf_lo(w.y); acc.w += bf_hi(w.y);
            }
            const float inv = 1.0f / (float)DEG;
            acc.x *= inv; acc.y *= inv; acc.z *= inv; acc.w *= inv;

            uint32_t h0, l0, h1, l1;
            bf16x2_split(self.x, self.y, h0, l0);
            bf16x2_split(self.z, self.w, h1, l1);
            xs_hi[wbase]     = h0;  xs_hi[wbase + 1] = h1;
            xs_lo[wbase]     = l0;  xs_lo[wbase + 1] = l1;

            bf16x2_split(acc.x, acc.y, h0, l0);
            bf16x2_split(acc.z, acc.w, h1, l1);
            xs_hi[wbase + 64] = h0; xs_hi[wbase + 65] = h1;
            xs_lo[wbase + 64] = l0; xs_lo[wbase + 65] = l1;
        } else {
            xs_hi[wbase] = 0u;      xs_hi[wbase + 1] = 0u;
            xs_lo[wbase] = 0u;      xs_lo[wbase + 1] = 0u;
            xs_hi[wbase + 64] = 0u; xs_hi[wbase + 65] = 0u;
            xs_lo[wbase + 64] = 0u; xs_lo[wbase + 65] = 0u;
        }
    }
    __syncthreads();

    // ---------------- Phase 2: bf16x3 GEMM, B direct from L2 ---------------
    // 8 warps, each owns M=32 x 32 N-cols (mt=2, nt=4); one reader per B frag.
    const int g  = lane >> 2;
    const int t  = lane & 3;
    const int n_base = wid * 32;

    float acc[2][4][4];
    #pragma unroll
    for (int mt = 0; mt < 2; mt++)
        #pragma unroll
        for (int nt = 0; nt < 4; nt++)
            #pragma unroll
            for (int r = 0; r < 4; r++)
                acc[mt][nt][r] = 0.f;

    // nblk = wid*4 + nt
    const uint4* wbase_p = g_wfrag + (wid * 4) * 32 + lane;

    #pragma unroll 2
    for (int ksg = 0; ksg < 16; ksg++) {
        uint4 bw[4];
        #pragma unroll
        for (int q = 0; q < 4; q++)
            bw[q] = wbase_p[(ksg * 32 + q) * 32];

        uint32_t ah[2][4], al[2][4];
        #pragma unroll
        for (int mt = 0; mt < 2; mt++) {
            const int r0 = mt * 16 + g;
            const int i00 = r0 * (XLD / 2) + ksg * 8 + t;
            const int i01 = (r0 + 8) * (XLD / 2) + ksg * 8 + t;
            ah[mt][0] = xs_hi[i00];     al[mt][0] = xs_lo[i00];
            ah[mt][1] = xs_hi[i01];     al[mt][1] = xs_lo[i01];
            ah[mt][2] = xs_hi[i00 + 4]; al[mt][2] = xs_lo[i00 + 4];
            ah[mt][3] = xs_hi[i01 + 4]; al[mt][3] = xs_lo[i01 + 4];
        }

        #pragma unroll
        for (int nt = 0; nt < 4; nt++) {
            #pragma unroll
            for (int mt = 0; mt < 2; mt++) {
                mma_bf16(acc[mt][nt], ah[mt], bw[nt].x, bw[nt].y);  // Ah*Bh
                mma_bf16(acc[mt][nt], al[mt], bw[nt].x, bw[nt].y);  // Al*Bh
                mma_bf16(acc[mt][nt], ah[mt], bw[nt].z, bw[nt].w);  // Ah*Bl
            }
        }
    }

    // ---------------- Phase 3: ReLU + store from registers -----------------
    #pragma unroll
    for (int mt = 0; mt < 2; mt++) {
        const int r0 = node0 + mt * 16 + g;
        #pragma unroll
        for (int nt = 0; nt < 4; nt++) {
            const int c0 = n_base + nt * 8 + t * 2;
            if (r0 < N_NODES) {
                float2 v0 = make_float2(fmaxf(acc[mt][nt][0], 0.f),
                                        fmaxf(acc[mt][nt][1], 0.f));
                *reinterpret_cast<float2*>(out + (long long)r0 * DOUT + c0) = v0;
            }
            if (r0 + 8 < N_NODES) {
                float2 v1 = make_float2(fmaxf(acc[mt][nt][2], 0.f),
                                        fmaxf(acc[mt][nt][3], 0.f));
                *reinterpret_cast<float2*>(out + (long long)(r0 + 8) * DOUT + c0) = v1;
            }
        }
    }
}

extern "C" void kernel_launch(void* const* d_in, const int* in_sizes, int n_in,
                              void* d_out, int out_size)
{
    const float* features = (const float*)d_in[0];
    const int*   edges    = (const int*)d_in[1];
    const float* kernel   = (const float*)d_in[2];
    float*       out      = (float*)d_out;
    (void)in_sizes; (void)n_in; (void)out_size;

    static bool attr_set = false;
    if (!attr_set) {
        cudaFuncSetAttribute(sage_fused_kernel,
                             cudaFuncAttributeMaxDynamicSharedMemorySize, SMEM_BYTES);
        attr_set = true;
    }

    f2bf_kernel<<<(N_NODES * (DFEAT / 2) + 255) / 256, 256>>>(features);
    wsplit_kernel<<<64, 256>>>(kernel);
    const int grid = (N_NODES + BM - 1) / BM;   // 1563
    sage_fused_kernel<<<grid, 256, SMEM_BYTES>>>(features, edges, out);
}

// round 13
// speedup vs baseline: 2.0039x; 1.0382x over previous
#include <cuda_runtime.h>
#include <cuda_bf16.h>
#include <cstdint>

#define N_NODES 50000
#define DEG     32
#define DFEAT   128
#define DIN     256
#define DOUT    256

#define BM 32
#define XLD 264          // bf16 row stride for xs (pad 8)

// smem: xs hi + lo
#define XS_HI_OFF 0u
#define XS_LO_OFF (BM * XLD * 2u)            // 16896
#define SMEM_BYTES (2u * BM * XLD * 2u)      // 33792

// W in fragment order: [ksg(16)][nblk(32)][lane(32)] -> uint4
__device__ uint4 g_wfrag[16 * 32 * 32];      // 256 KB

// bf16 copy of features, packed 2 cols/word: [node][64] uint32
__device__ uint32_t g_fh[N_NODES * (DFEAT / 2)];   // 12.8 MB

__device__ __forceinline__ void bf16x2_split(float x, float y,
                                             uint32_t& hi, uint32_t& lo) {
    __nv_bfloat162 h = __float22bfloat162_rn(make_float2(x, y));
    float2 hf = __bfloat1622float2(h);
    __nv_bfloat162 l = __float22bfloat162_rn(make_float2(x - hf.x, y - hf.y));
    hi = *reinterpret_cast<uint32_t*>(&h);
    lo = *reinterpret_cast<uint32_t*>(&l);
}

__device__ __forceinline__ void mma_bf16(float* d, const uint32_t* a,
                                         uint32_t b0, uint32_t b1) {
    asm volatile(
        "mma.sync.aligned.m16n8k16.row.col.f32.bf16.bf16.f32 "
        "{%0,%1,%2,%3}, {%4,%5,%6,%7}, {%8,%9}, {%0,%1,%2,%3};"
        : "+f"(d[0]), "+f"(d[1]), "+f"(d[2]), "+f"(d[3])
        : "r"(a[0]), "r"(a[1]), "r"(a[2]), "r"(a[3]),
          "r"(b0), "r"(b1));
}

// exact bf16(packed low/high) -> fp32
__device__ __forceinline__ float bf_lo(uint32_t w) { return __uint_as_float(w << 16); }
__device__ __forceinline__ float bf_hi(uint32_t w) { return __uint_as_float(w & 0xFFFF0000u); }

// ------------- prologue A: features -> packed bf16 table (vectorized) ------
// Each thread: 8 floats = two float4 loads -> one uint4 store. 800k threads.
__global__ void f2bf_kernel(const float* __restrict__ F) {
    const int idx = blockIdx.x * blockDim.x + threadIdx.x;   // uint4 index
    // total uint4 elems = N_NODES * DFEAT / 8 = 800000
    const float4 v0 = *reinterpret_cast<const float4*>(F + idx * 8);
    const float4 v1 = *reinterpret_cast<const float4*>(F + idx * 8 + 4);
    __nv_bfloat162 p0 = __float22bfloat162_rn(make_float2(v0.x, v0.y));
    __nv_bfloat162 p1 = __float22bfloat162_rn(make_float2(v0.z, v0.w));
    __nv_bfloat162 p2 = __float22bfloat162_rn(make_float2(v1.x, v1.y));
    __nv_bfloat162 p3 = __float22bfloat162_rn(make_float2(v1.z, v1.w));
    uint4 o;
    o.x = *reinterpret_cast<uint32_t*>(&p0);
    o.y = *reinterpret_cast<uint32_t*>(&p1);
    o.z = *reinterpret_cast<uint32_t*>(&p2);
    o.w = *reinterpret_cast<uint32_t*>(&p3);
    *reinterpret_cast<uint4*>(g_fh + idx * 4) = o;
}

// ------------- prologue B: split W into fragment-ordered uint4 -------------
__global__ void wsplit_kernel(const float* __restrict__ W) {
    const int idx = blockIdx.x * blockDim.x + threadIdx.x;   // 16384
    const int lane = idx & 31;
    const int nblk = (idx >> 5) & 31;
    const int ksg  = idx >> 10;            // 0..15
    const int g = lane >> 2, t = lane & 3;
    const int n  = nblk * 8 + g;
    const int k0 = ksg * 16 + 2 * t;
    const int k1 = k0 + 8;

    uint4 v;
    bf16x2_split(W[k0 * DOUT + n], W[(k0 + 1) * DOUT + n], v.x, v.z);
    bf16x2_split(W[k1 * DOUT + n], W[(k1 + 1) * DOUT + n], v.y, v.w);
    g_wfrag[idx] = v;
}

// ------------------------------ fused kernel -------------------------------
__global__ __launch_bounds__(256, 3)
void sage_fused_kernel(const float* __restrict__ features,
                       const int* __restrict__ edges,
                       float* __restrict__ out)
{
    extern __shared__ char sm[];
    uint32_t* xs_hi = reinterpret_cast<uint32_t*>(sm + XS_HI_OFF);
    uint32_t* xs_lo = reinterpret_cast<uint32_t*>(sm + XS_LO_OFF);

    const int tid  = threadIdx.x;
    const int lane = tid & 31;
    const int wid  = tid >> 5;            // 0..7
    const int node0 = blockIdx.x * BM;

    // ---------------- Phase 1: gather (bf16 table) + mean + split ----------
    #pragma unroll
    for (int s = 0; s < BM / 8; s++) {
        const int m = wid * (BM / 8) + s;
        const int node = node0 + m;
        const int wbase = m * (XLD / 2) + lane * 2;
        if (node < N_NODES) {
            const int my_e = edges[node * DEG + lane];
            const float4 self = *reinterpret_cast<const float4*>(
                features + (long long)node * DFEAT + lane * 4);

            float4 acc = make_float4(0.f, 0.f, 0.f, 0.f);
            #pragma unroll
            for (int j = 0; j < DEG; j++) {
                const int idx = __shfl_sync(0xffffffffu, my_e, j);
                const uint2 w = *reinterpret_cast<const uint2*>(
                    g_fh + idx * (DFEAT / 2) + lane * 2);
                acc.x += bf_lo(w.x); acc.y += bf_hi(w.x);
                acc.z += bf_lo(w.y); acc.w += bf_hi(w.y);
            }
            const float inv = 1.0f / (float)DEG;
            acc.x *= inv; acc.y *= inv; acc.z *= inv; acc.w *= inv;

            uint32_t h0, l0, h1, l1;
            bf16x2_split(self.x, self.y, h0, l0);
            bf16x2_split(self.z, self.w, h1, l1);
            xs_hi[wbase]     = h0;  xs_hi[wbase + 1] = h1;
            xs_lo[wbase]     = l0;  xs_lo[wbase + 1] = l1;

            bf16x2_split(acc.x, acc.y, h0, l0);
            bf16x2_split(acc.z, acc.w, h1, l1);
            xs_hi[wbase + 64] = h0; xs_hi[wbase + 65] = h1;
            xs_lo[wbase + 64] = l0; xs_lo[wbase + 65] = l1;
        } else {
            xs_hi[wbase] = 0u;      xs_hi[wbase + 1] = 0u;
            xs_lo[wbase] = 0u;      xs_lo[wbase + 1] = 0u;
            xs_hi[wbase + 64] = 0u; xs_hi[wbase + 65] = 0u;
            xs_lo[wbase + 64] = 0u; xs_lo[wbase + 65] = 0u;
        }
    }
    __syncthreads();

    // ---------------- Phase 2: bf16x3 GEMM, B direct from L2 ---------------
    const int g  = lane >> 2;
    const int t  = lane & 3;
    const int n_base = wid * 32;

    float acc[2][4][4];
    #pragma unroll
    for (int mt = 0; mt < 2; mt++)
        #pragma unroll
        for (int nt = 0; nt < 4; nt++)
            #pragma unroll
            for (int r = 0; r < 4; r++)
                acc[mt][nt][r] = 0.f;

    // nblk = wid*4 + nt
    const uint4* wbase_p = g_wfrag + (wid * 4) * 32 + lane;

    #pragma unroll 2
    for (int ksg = 0; ksg < 16; ksg++) {
        uint4 bw[4];
        #pragma unroll
        for (int q = 0; q < 4; q++)
            bw[q] = wbase_p[(ksg * 32 + q) * 32];

        uint32_t ah[2][4], al[2][4];
        #pragma unroll
        for (int mt = 0; mt < 2; mt++) {
            const int r0 = mt * 16 + g;
            const int i00 = r0 * (XLD / 2) + ksg * 8 + t;
            const int i01 = (r0 + 8) * (XLD / 2) + ksg * 8 + t;
            ah[mt][0] = xs_hi[i00];     al[mt][0] = xs_lo[i00];
            ah[mt][1] = xs_hi[i01];     al[mt][1] = xs_lo[i01];
            ah[mt][2] = xs_hi[i00 + 4]; al[mt][2] = xs_lo[i00 + 4];
            ah[mt][3] = xs_hi[i01 + 4]; al[mt][3] = xs_lo[i01 + 4];
        }

        #pragma unroll
        for (int nt = 0; nt < 4; nt++) {
            #pragma unroll
            for (int mt = 0; mt < 2; mt++) {
                mma_bf16(acc[mt][nt], ah[mt], bw[nt].x, bw[nt].y);  // Ah*Bh
                mma_bf16(acc[mt][nt], al[mt], bw[nt].x, bw[nt].y);  // Al*Bh
                mma_bf16(acc[mt][nt], ah[mt], bw[nt].z, bw[nt].w);  // Ah*Bl
            }
        }
    }

    // ---------------- Phase 3: ReLU + store from registers -----------------
    #pragma unroll
    for (int mt = 0; mt < 2; mt++) {
        const int r0 = node0 + mt * 16 + g;
        #pragma unroll
        for (int nt = 0; nt < 4; nt++) {
            const int c0 = n_base + nt * 8 + t * 2;
            if (r0 < N_NODES) {
                float2 v0 = make_float2(fmaxf(acc[mt][nt][0], 0.f),
                                        fmaxf(acc[mt][nt][1], 0.f));
                *reinterpret_cast<float2*>(out + (long long)r0 * DOUT + c0) = v0;
            }
            if (r0 + 8 < N_NODES) {
                float2 v1 = make_float2(fmaxf(acc[mt][nt][2], 0.f),
                                        fmaxf(acc[mt][nt][3], 0.f));
                *reinterpret_cast<float2*>(out + (long long)(r0 + 8) * DOUT + c0) = v1;
            }
        }
    }
}

extern "C" void kernel_launch(void* const* d_in, const int* in_sizes, int n_in,
                              void* d_out, int out_size)
{
    const float* features = (const float*)d_in[0];
    const int*   edges    = (const int*)d_in[1];
    const float* kernel   = (const float*)d_in[2];
    float*       out      = (float*)d_out;
    (void)in_sizes; (void)n_in; (void)out_size;

    static bool attr_set = false;
    if (!attr_set) {
        cudaFuncSetAttribute(sage_fused_kernel,
                             cudaFuncAttributeMaxDynamicSharedMemorySize, SMEM_BYTES);
        attr_set = true;
    }

    // 800000 uint4 elems / 256 = 3125 blocks
    f2bf_kernel<<<(N_NODES * DFEAT / 8) / 256, 256>>>(features);
    wsplit_kernel<<<64, 256>>>(kernel);
    const int grid = (N_NODES + BM - 1) / BM;   // 1563
    sage_fused_kernel<<<grid, 256, SMEM_BYTES>>>(features, edges, out);
}

// round 14
// speedup vs baseline: 2.2138x; 1.1047x over previous
#include <cuda_runtime.h>
#include <cuda_fp16.h>
#include <cstdint>

#define N_NODES 50000
#define DEG     32
#define DFEAT   128
#define DIN     256
#define DOUT    256

#define BM 32
#define XLD 264          // fp16 row stride for xs (pad 8)

// smem: xs hi + lo
#define XS_HI_OFF 0u
#define XS_LO_OFF (BM * XLD * 2u)            // 16896
#define SMEM_BYTES (2u * BM * XLD * 2u)      // 33792

// W (single fp16) in fragment order: [ksg(16)][nblk(32)][lane(32)] -> uint2
__device__ uint2 g_wfrag[16 * 32 * 32];      // 128 KB

// fp16 copy of features, packed 2 cols/word: [node][64] uint32
__device__ uint32_t g_fh[N_NODES * (DFEAT / 2)];   // 12.8 MB

__device__ __forceinline__ void f16x2_split(float x, float y,
                                            uint32_t& hi, uint32_t& lo) {
    __half2 h = __float22half2_rn(make_float2(x, y));
    float2 hf = __half22float2(h);
    __half2 l = __float22half2_rn(make_float2(x - hf.x, y - hf.y));
    hi = *reinterpret_cast<uint32_t*>(&h);
    lo = *reinterpret_cast<uint32_t*>(&l);
}

__device__ __forceinline__ void mma_f16(float* d, const uint32_t* a,
                                        uint32_t b0, uint32_t b1) {
    asm volatile(
        "mma.sync.aligned.m16n8k16.row.col.f32.f16.f16.f32 "
        "{%0,%1,%2,%3}, {%4,%5,%6,%7}, {%8,%9}, {%0,%1,%2,%3};"
        : "+f"(d[0]), "+f"(d[1]), "+f"(d[2]), "+f"(d[3])
        : "r"(a[0]), "r"(a[1]), "r"(a[2]), "r"(a[3]),
          "r"(b0), "r"(b1));
}

// ------------- prologue A: features -> packed fp16 table (vectorized) ------
__global__ void f2h_kernel(const float* __restrict__ F) {
    const int idx = blockIdx.x * blockDim.x + threadIdx.x;   // uint4 index
    const float4 v0 = *reinterpret_cast<const float4*>(F + idx * 8);
    const float4 v1 = *reinterpret_cast<const float4*>(F + idx * 8 + 4);
    __half2 p0 = __float22half2_rn(make_float2(v0.x, v0.y));
    __half2 p1 = __float22half2_rn(make_float2(v0.z, v0.w));
    __half2 p2 = __float22half2_rn(make_float2(v1.x, v1.y));
    __half2 p3 = __float22half2_rn(make_float2(v1.z, v1.w));
    uint4 o;
    o.x = *reinterpret_cast<uint32_t*>(&p0);
    o.y = *reinterpret_cast<uint32_t*>(&p1);
    o.z = *reinterpret_cast<uint32_t*>(&p2);
    o.w = *reinterpret_cast<uint32_t*>(&p3);
    *reinterpret_cast<uint4*>(g_fh + idx * 4) = o;
}

// ------------- prologue B: W -> fp16 fragment-ordered uint2 ----------------
__global__ void wsplit_kernel(const float* __restrict__ W) {
    const int idx = blockIdx.x * blockDim.x + threadIdx.x;   // 16384
    const int lane = idx & 31;
    const int nblk = (idx >> 5) & 31;
    const int ksg  = idx >> 10;            // 0..15
    const int g = lane >> 2, t = lane & 3;
    const int n  = nblk * 8 + g;
    const int k0 = ksg * 16 + 2 * t;
    const int k1 = k0 + 8;

    __half2 b0 = __float22half2_rn(make_float2(W[k0 * DOUT + n], W[(k0 + 1) * DOUT + n]));
    __half2 b1 = __float22half2_rn(make_float2(W[k1 * DOUT + n], W[(k1 + 1) * DOUT + n]));
    uint2 v;
    v.x = *reinterpret_cast<uint32_t*>(&b0);
    v.y = *reinterpret_cast<uint32_t*>(&b1);
    g_wfrag[idx] = v;
}

// ------------------------------ fused kernel -------------------------------
__global__ __launch_bounds__(256, 3)
void sage_fused_kernel(const float* __restrict__ features,
                       const int* __restrict__ edges,
                       float* __restrict__ out)
{
    extern __shared__ char sm[];
    uint32_t* xs_hi = reinterpret_cast<uint32_t*>(sm + XS_HI_OFF);
    uint32_t* xs_lo = reinterpret_cast<uint32_t*>(sm + XS_LO_OFF);

    const int tid  = threadIdx.x;
    const int lane = tid & 31;
    const int wid  = tid >> 5;            // 0..7
    const int node0 = blockIdx.x * BM;

    // ---------------- Phase 1: gather (fp16 table) + mean + split ----------
    #pragma unroll
    for (int s = 0; s < BM / 8; s++) {
        const int m = wid * (BM / 8) + s;
        const int node = node0 + m;
        const int wbase = m * (XLD / 2) + lane * 2;
        if (node < N_NODES) {
            const int my_e = edges[node * DEG + lane];
            const float4 self = *reinterpret_cast<const float4*>(
                features + (long long)node * DFEAT + lane * 4);

            float4 acc = make_float4(0.f, 0.f, 0.f, 0.f);
            #pragma unroll
            for (int j = 0; j < DEG; j++) {
                const int idx = __shfl_sync(0xffffffffu, my_e, j);
                const uint2 w = *reinterpret_cast<const uint2*>(
                    g_fh + idx * (DFEAT / 2) + lane * 2);
                const float2 f0 = __half22float2(*reinterpret_cast<const __half2*>(&w.x));
                const float2 f1 = __half22float2(*reinterpret_cast<const __half2*>(&w.y));
                acc.x += f0.x; acc.y += f0.y;
                acc.z += f1.x; acc.w += f1.y;
            }
            const float inv = 1.0f / (float)DEG;
            acc.x *= inv; acc.y *= inv; acc.z *= inv; acc.w *= inv;

            uint32_t h0, l0, h1, l1;
            f16x2_split(self.x, self.y, h0, l0);
            f16x2_split(self.z, self.w, h1, l1);
            xs_hi[wbase]     = h0;  xs_hi[wbase + 1] = h1;
            xs_lo[wbase]     = l0;  xs_lo[wbase + 1] = l1;

            f16x2_split(acc.x, acc.y, h0, l0);
            f16x2_split(acc.z, acc.w, h1, l1);
            xs_hi[wbase + 64] = h0; xs_hi[wbase + 65] = h1;
            xs_lo[wbase + 64] = l0; xs_lo[wbase + 65] = l1;
        } else {
            xs_hi[wbase] = 0u;      xs_hi[wbase + 1] = 0u;
            xs_lo[wbase] = 0u;      xs_lo[wbase + 1] = 0u;
            xs_hi[wbase + 64] = 0u; xs_hi[wbase + 65] = 0u;
            xs_lo[wbase + 64] = 0u; xs_lo[wbase + 65] = 0u;
        }
    }
    __syncthreads();

    // ---------------- Phase 2: fp16x2 GEMM, B direct from L2 ---------------
    // 8 warps, each owns M=32 x 32 N-cols (mt=2, nt=4); one reader per B frag.
    // Terms: Ah*W + Al*W (A = fp16 hi+lo 22-bit; W = single fp16).
    const int g  = lane >> 2;
    const int t  = lane & 3;
    const int n_base = wid * 32;

    float acc[2][4][4];
    #pragma unroll
    for (int mt = 0; mt < 2; mt++)
        #pragma unroll
        for (int nt = 0; nt < 4; nt++)
            #pragma unroll
            for (int r = 0; r < 4; r++)
                acc[mt][nt][r] = 0.f;

    // nblk = wid*4 + nt
    const uint2* wbase_p = g_wfrag + (wid * 4) * 32 + lane;

    #pragma unroll 2
    for (int ksg = 0; ksg < 16; ksg++) {
        uint2 bw[4];
        #pragma unroll
        for (int q = 0; q < 4; q++)
            bw[q] = wbase_p[(ksg * 32 + q) * 32];

        uint32_t ah[2][4], al[2][4];
        #pragma unroll
        for (int mt = 0; mt < 2; mt++) {
            const int r0 = mt * 16 + g;
            const int i00 = r0 * (XLD / 2) + ksg * 8 + t;
            const int i01 = (r0 + 8) * (XLD / 2) + ksg * 8 + t;
            ah[mt][0] = xs_hi[i00];     al[mt][0] = xs_lo[i00];
            ah[mt][1] = xs_hi[i01];     al[mt][1] = xs_lo[i01];
            ah[mt][2] = xs_hi[i00 + 4]; al[mt][2] = xs_lo[i00 + 4];
            ah[mt][3] = xs_hi[i01 + 4]; al[mt][3] = xs_lo[i01 + 4];
        }

        #pragma unroll
        for (int nt = 0; nt < 4; nt++) {
            #pragma unroll
            for (int mt = 0; mt < 2; mt++) {
                mma_f16(acc[mt][nt], ah[mt], bw[nt].x, bw[nt].y);  // Ah*W
                mma_f16(acc[mt][nt], al[mt], bw[nt].x, bw[nt].y);  // Al*W
            }
        }
    }

    // ---------------- Phase 3: ReLU + store from registers -----------------
    #pragma unroll
    for (int mt = 0; mt < 2; mt++) {
        const int r0 = node0 + mt * 16 + g;
        #pragma unroll
        for (int nt = 0; nt < 4; nt++) {
            const int c0 = n_base + nt * 8 + t * 2;
            if (r0 < N_NODES) {
                float2 v0 = make_float2(fmaxf(acc[mt][nt][0], 0.f),
                                        fmaxf(acc[mt][nt][1], 0.f));
                *reinterpret_cast<float2*>(out + (long long)r0 * DOUT + c0) = v0;
            }
            if (r0 + 8 < N_NODES) {
                float2 v1 = make_float2(fmaxf(acc[mt][nt][2], 0.f),
                                        fmaxf(acc[mt][nt][3], 0.f));
                *reinterpret_cast<float2*>(out + (long long)(r0 + 8) * DOUT + c0) = v1;
            }
        }
    }
}

extern "C" void kernel_launch(void* const* d_in, const int* in_sizes, int n_in,
                              void* d_out, int out_size)
{
    const float* features = (const float*)d_in[0];
    const int*   edges    = (const int*)d_in[1];
    const float* kernel   = (const float*)d_in[2];
    float*       out      = (float*)d_out;
    (void)in_sizes; (void)n_in; (void)out_size;

    static bool attr_set = false;
    if (!attr_set) {
        cudaFuncSetAttribute(sage_fused_kernel,
                             cudaFuncAttributeMaxDynamicSharedMemorySize, SMEM_BYTES);
        attr_set = true;
    }

    f2h_kernel<<<(N_NODES * DFEAT / 8) / 256, 256>>>(features);
    wsplit_kernel<<<64, 256>>>(kernel);
    const int grid = (N_NODES + BM - 1) / BM;   // 1563
    sage_fused_kernel<<<grid, 256, SMEM_BYTES>>>(features, edges, out);
}

// round 15
// speedup vs baseline: 2.2776x; 1.0288x over previous
#include <cuda_runtime.h>
#include <cuda_fp16.h>
#include <cstdint>

#define N_NODES 50000
#define DEG     32
#define DFEAT   128
#define DIN     256
#define DOUT    256

#define BM 32
#define XLD 264          // fp16 row stride for xs (pad 8)

// smem: xs hi + lo
#define XS_HI_OFF 0u
#define XS_LO_OFF (BM * XLD * 2u)            // 16896
#define SMEM_BYTES (2u * BM * XLD * 2u)      // 33792

// W (single fp16) in fragment order: [ksg(16)][nblk(32)][lane(32)] -> uint2
__device__ uint2 g_wfrag[16 * 32 * 32];      // 128 KB

// fp16 copy of features, packed 2 cols/word: [node][64] uint32
__device__ uint32_t g_fh[N_NODES * (DFEAT / 2)];   // 12.8 MB

__device__ __forceinline__ void f16x2_split(float x, float y,
                                            uint32_t& hi, uint32_t& lo) {
    __half2 h = __float22half2_rn(make_float2(x, y));
    float2 hf = __half22float2(h);
    __half2 l = __float22half2_rn(make_float2(x - hf.x, y - hf.y));
    hi = *reinterpret_cast<uint32_t*>(&h);
    lo = *reinterpret_cast<uint32_t*>(&l);
}

__device__ __forceinline__ void mma_f16(float* d, const uint32_t* a,
                                        uint32_t b0, uint32_t b1) {
    asm volatile(
        "mma.sync.aligned.m16n8k16.row.col.f32.f16.f16.f32 "
        "{%0,%1,%2,%3}, {%4,%5,%6,%7}, {%8,%9}, {%0,%1,%2,%3};"
        : "+f"(d[0]), "+f"(d[1]), "+f"(d[2]), "+f"(d[3])
        : "r"(a[0]), "r"(a[1]), "r"(a[2]), "r"(a[3]),
          "r"(b0), "r"(b1));
}

// ------------- prologue A: features -> packed fp16 table (16 floats/thr) ---
__global__ void f2h_kernel(const float* __restrict__ F) {
    const long long base = (long long)(blockIdx.x * blockDim.x + threadIdx.x) * 16;
    // total floats = N_NODES*DFEAT = 6.4M; 400000 threads
    float4 v[4];
    #pragma unroll
    for (int i = 0; i < 4; i++)
        v[i] = *reinterpret_cast<const float4*>(F + base + i * 4);

    uint4 o[2];
    #pragma unroll
    for (int i = 0; i < 2; i++) {
        __half2 p0 = __float22half2_rn(make_float2(v[i*2].x,   v[i*2].y));
        __half2 p1 = __float22half2_rn(make_float2(v[i*2].z,   v[i*2].w));
        __half2 p2 = __float22half2_rn(make_float2(v[i*2+1].x, v[i*2+1].y));
        __half2 p3 = __float22half2_rn(make_float2(v[i*2+1].z, v[i*2+1].w));
        o[i].x = *reinterpret_cast<uint32_t*>(&p0);
        o[i].y = *reinterpret_cast<uint32_t*>(&p1);
        o[i].z = *reinterpret_cast<uint32_t*>(&p2);
        o[i].w = *reinterpret_cast<uint32_t*>(&p3);
    }
    *reinterpret_cast<uint4*>(g_fh + base / 2)     = o[0];
    *reinterpret_cast<uint4*>(g_fh + base / 2 + 4) = o[1];
}

// ------------- prologue B: W -> fp16 fragment-ordered uint2 ----------------
__global__ void wsplit_kernel(const float* __restrict__ W) {
    const int idx = blockIdx.x * blockDim.x + threadIdx.x;   // 16384
    const int lane = idx & 31;
    const int nblk = (idx >> 5) & 31;
    const int ksg  = idx >> 10;            // 0..15
    const int g = lane >> 2, t = lane & 3;
    const int n  = nblk * 8 + g;
    const int k0 = ksg * 16 + 2 * t;
    const int k1 = k0 + 8;

    __half2 b0 = __float22half2_rn(make_float2(W[k0 * DOUT + n], W[(k0 + 1) * DOUT + n]));
    __half2 b1 = __float22half2_rn(make_float2(W[k1 * DOUT + n], W[(k1 + 1) * DOUT + n]));
    uint2 v;
    v.x = *reinterpret_cast<uint32_t*>(&b0);
    v.y = *reinterpret_cast<uint32_t*>(&b1);
    g_wfrag[idx] = v;
}

// ------------------------------ fused kernel -------------------------------
__global__ __launch_bounds__(256, 4)
void sage_fused_kernel(const float* __restrict__ features,
                       const int* __restrict__ edges,
                       float* __restrict__ out)
{
    extern __shared__ char sm[];
    uint32_t* xs_hi = reinterpret_cast<uint32_t*>(sm + XS_HI_OFF);
    uint32_t* xs_lo = reinterpret_cast<uint32_t*>(sm + XS_LO_OFF);

    const int tid  = threadIdx.x;
    const int lane = tid & 31;
    const int wid  = tid >> 5;            // 0..7
    const int node0 = blockIdx.x * BM;

    // ---------------- Phase 1: gather (fp16 table) + mean + split ----------
    #pragma unroll
    for (int s = 0; s < BM / 8; s++) {
        const int m = wid * (BM / 8) + s;
        const int node = node0 + m;
        const int wbase = m * (XLD / 2) + lane * 2;
        if (node < N_NODES) {
            const int my_e = edges[node * DEG + lane];
            const float4 self = *reinterpret_cast<const float4*>(
                features + (long long)node * DFEAT + lane * 4);

            float4 acc = make_float4(0.f, 0.f, 0.f, 0.f);
            #pragma unroll
            for (int j = 0; j < DEG; j++) {
                const int idx = __shfl_sync(0xffffffffu, my_e, j);
                const uint2 w = *reinterpret_cast<const uint2*>(
                    g_fh + idx * (DFEAT / 2) + lane * 2);
                const float2 f0 = __half22float2(*reinterpret_cast<const __half2*>(&w.x));
                const float2 f1 = __half22float2(*reinterpret_cast<const __half2*>(&w.y));
                acc.x += f0.x; acc.y += f0.y;
                acc.z += f1.x; acc.w += f1.y;
            }
            const float inv = 1.0f / (float)DEG;
            acc.x *= inv; acc.y *= inv; acc.z *= inv; acc.w *= inv;

            uint32_t h0, l0, h1, l1;
            f16x2_split(self.x, self.y, h0, l0);
            f16x2_split(self.z, self.w, h1, l1);
            xs_hi[wbase]     = h0;  xs_hi[wbase + 1] = h1;
            xs_lo[wbase]     = l0;  xs_lo[wbase + 1] = l1;

            f16x2_split(acc.x, acc.y, h0, l0);
            f16x2_split(acc.z, acc.w, h1, l1);
            xs_hi[wbase + 64] = h0; xs_hi[wbase + 65] = h1;
            xs_lo[wbase + 64] = l0; xs_lo[wbase + 65] = l1;
        } else {
            xs_hi[wbase] = 0u;      xs_hi[wbase + 1] = 0u;
            xs_lo[wbase] = 0u;      xs_lo[wbase + 1] = 0u;
            xs_hi[wbase + 64] = 0u; xs_hi[wbase + 65] = 0u;
            xs_lo[wbase + 64] = 0u; xs_lo[wbase + 65] = 0u;
        }
    }
    __syncthreads();

    // ---------------- Phase 2: fp16x2 GEMM, B direct from L2 ---------------
    // 8 warps, each owns M=32 x 32 N-cols; mt SEQUENTIAL to fit 64 regs.
    const int g  = lane >> 2;
    const int t  = lane & 3;
    const int n_base = wid * 32;

    float acc[2][4][4];
    #pragma unroll
    for (int mt = 0; mt < 2; mt++)
        #pragma unroll
        for (int nt = 0; nt < 4; nt++)
            #pragma unroll
            for (int r = 0; r < 4; r++)
                acc[mt][nt][r] = 0.f;

    // nblk = wid*4 + nt
    const uint2* wbase_p = g_wfrag + (wid * 4) * 32 + lane;

    #pragma unroll 1
    for (int ksg = 0; ksg < 16; ksg++) {
        uint2 bw[4];
        #pragma unroll
        for (int q = 0; q < 4; q++)
            bw[q] = wbase_p[(ksg * 32 + q) * 32];

        #pragma unroll
        for (int mt = 0; mt < 2; mt++) {
            const int r0 = mt * 16 + g;
            const int i00 = r0 * (XLD / 2) + ksg * 8 + t;
            const int i01 = (r0 + 8) * (XLD / 2) + ksg * 8 + t;
            uint32_t ah[4], al[4];
            ah[0] = xs_hi[i00];     al[0] = xs_lo[i00];
            ah[1] = xs_hi[i01];     al[1] = xs_lo[i01];
            ah[2] = xs_hi[i00 + 4]; al[2] = xs_lo[i00 + 4];
            ah[3] = xs_hi[i01 + 4]; al[3] = xs_lo[i01 + 4];

            #pragma unroll
            for (int nt = 0; nt < 4; nt++) {
                mma_f16(acc[mt][nt], ah, bw[nt].x, bw[nt].y);  // Ah*W
                mma_f16(acc[mt][nt], al, bw[nt].x, bw[nt].y);  // Al*W
            }
        }
    }

    // ---------------- Phase 3: ReLU + store from registers -----------------
    #pragma unroll
    for (int mt = 0; mt < 2; mt++) {
        const int r0 = node0 + mt * 16 + g;
        #pragma unroll
        for (int nt = 0; nt < 4; nt++) {
            const int c0 = n_base + nt * 8 + t * 2;
            if (r0 < N_NODES) {
                float2 v0 = make_float2(fmaxf(acc[mt][nt][0], 0.f),
                                        fmaxf(acc[mt][nt][1], 0.f));
                *reinterpret_cast<float2*>(out + (long long)r0 * DOUT + c0) = v0;
            }
            if (r0 + 8 < N_NODES) {
                float2 v1 = make_float2(fmaxf(acc[mt][nt][2], 0.f),
                                        fmaxf(acc[mt][nt][3], 0.f));
                *reinterpret_cast<float2*>(out + (long long)(r0 + 8) * DOUT + c0) = v1;
            }
        }
    }
}

extern "C" void kernel_launch(void* const* d_in, const int* in_sizes, int n_in,
                              void* d_out, int out_size)
{
    const float* features = (const float*)d_in[0];
    const int*   edges    = (const int*)d_in[1];
    const float* kernel   = (const float*)d_in[2];
    float*       out      = (float*)d_out;
    (void)in_sizes; (void)n_in; (void)out_size;

    static bool attr_set = false;
    if (!attr_set) {
        cudaFuncSetAttribute(sage_fused_kernel,
                             cudaFuncAttributeMaxDynamicSharedMemorySize, SMEM_BYTES);
        attr_set = true;
    }

    // 6.4M floats / 16 per thread / 256 = 1563 blocks (exact: 400000/256=1562.5 -> 1563)
    f2h_kernel<<<(N_NODES * DFEAT / 16 + 255) / 256, 256>>>(features);
    wsplit_kernel<<<64, 256>>>(kernel);
    const int grid = (N_NODES + BM - 1) / BM;   // 1563
    sage_fused_kernel<<<grid, 256, SMEM_BYTES>>>(features, edges, out);
}

// round 16
// speedup vs baseline: 2.3441x; 1.0292x over previous
#include <cuda_runtime.h>
#include <cuda_fp16.h>
#include <cstdint>

#define N_NODES 50000
#define DEG     32
#define DFEAT   128
#define DIN     256
#define DOUT    256

#define BM 32
#define XLD 264          // fp16 row stride for xs (pad 8)

// smem: xs hi + lo
#define XS_HI_OFF 0u
#define XS_LO_OFF (BM * XLD * 2u)            // 16896
#define SMEM_BYTES (2u * BM * XLD * 2u)      // 33792

// W (single fp16) in fragment order: [ksg(16)][nblk(32)][lane(32)] -> uint2
__device__ uint2 g_wfrag[16 * 32 * 32];      // 128 KB

// fp16 copy of features, packed 2 cols/word: [node][64] uint32
__device__ uint32_t g_fh[N_NODES * (DFEAT / 2)];   // 12.8 MB

__device__ __forceinline__ void f16x2_split(float x, float y,
                                            uint32_t& hi, uint32_t& lo) {
    __half2 h = __float22half2_rn(make_float2(x, y));
    float2 hf = __half22float2(h);
    __half2 l = __float22half2_rn(make_float2(x - hf.x, y - hf.y));
    hi = *reinterpret_cast<uint32_t*>(&h);
    lo = *reinterpret_cast<uint32_t*>(&l);
}

__device__ __forceinline__ void mma_f16(float* d, const uint32_t* a,
                                        uint32_t b0, uint32_t b1) {
    asm volatile(
        "mma.sync.aligned.m16n8k16.row.col.f32.f16.f16.f32 "
        "{%0,%1,%2,%3}, {%4,%5,%6,%7}, {%8,%9}, {%0,%1,%2,%3};"
        : "+f"(d[0]), "+f"(d[1]), "+f"(d[2]), "+f"(d[3])
        : "r"(a[0]), "r"(a[1]), "r"(a[2]), "r"(a[3]),
          "r"(b0), "r"(b1));
}

// ------------- prologue A: features -> packed fp16 table (8 floats/thr) ----
__global__ void f2h_kernel(const float* __restrict__ F) {
    const int idx = blockIdx.x * blockDim.x + threadIdx.x;   // uint4 index
    const float4 v0 = *reinterpret_cast<const float4*>(F + idx * 8);
    const float4 v1 = *reinterpret_cast<const float4*>(F + idx * 8 + 4);
    __half2 p0 = __float22half2_rn(make_float2(v0.x, v0.y));
    __half2 p1 = __float22half2_rn(make_float2(v0.z, v0.w));
    __half2 p2 = __float22half2_rn(make_float2(v1.x, v1.y));
    __half2 p3 = __float22half2_rn(make_float2(v1.z, v1.w));
    uint4 o;
    o.x = *reinterpret_cast<uint32_t*>(&p0);
    o.y = *reinterpret_cast<uint32_t*>(&p1);
    o.z = *reinterpret_cast<uint32_t*>(&p2);
    o.w = *reinterpret_cast<uint32_t*>(&p3);
    *reinterpret_cast<uint4*>(g_fh + idx * 4) = o;
}

// ------------- prologue B: W -> fp16 fragment-ordered uint2 ----------------
__global__ void wsplit_kernel(const float* __restrict__ W) {
    const int idx = blockIdx.x * blockDim.x + threadIdx.x;   // 16384
    const int lane = idx & 31;
    const int nblk = (idx >> 5) & 31;
    const int ksg  = idx >> 10;            // 0..15
    const int g = lane >> 2, t = lane & 3;
    const int n  = nblk * 8 + g;
    const int k0 = ksg * 16 + 2 * t;
    const int k1 = k0 + 8;

    __half2 b0 = __float22half2_rn(make_float2(W[k0 * DOUT + n], W[(k0 + 1) * DOUT + n]));
    __half2 b1 = __float22half2_rn(make_float2(W[k1 * DOUT + n], W[(k1 + 1) * DOUT + n]));
    uint2 v;
    v.x = *reinterpret_cast<uint32_t*>(&b0);
    v.y = *reinterpret_cast<uint32_t*>(&b1);
    g_wfrag[idx] = v;
}

// ------------------------------ fused kernel -------------------------------
__global__ __launch_bounds__(256, 4)
void sage_fused_kernel(const float* __restrict__ features,
                       const int* __restrict__ edges,
                       float* __restrict__ out)
{
    extern __shared__ char sm[];
    uint32_t* xs_hi = reinterpret_cast<uint32_t*>(sm + XS_HI_OFF);
    uint32_t* xs_lo = reinterpret_cast<uint32_t*>(sm + XS_LO_OFF);

    const int tid  = threadIdx.x;
    const int lane = tid & 31;
    const int wid  = tid >> 5;            // 0..7
    const int node0 = blockIdx.x * BM;

    // ---------------- Phase 1: gather (2 rows per LDG.128) + mean + split --
    // Lanes 0-15 take even neighbor rows, lanes 16-31 odd rows; each lane
    // covers 8 fp16 cols [8*(lane&15) .. +8). One shfl_down(16) pass merges.
    const int half = lane >> 4;           // 0 or 1
    const int lL   = lane & 15;

    #pragma unroll
    for (int s = 0; s < BM / 8; s++) {
        const int m = wid * (BM / 8) + s;
        const int node = node0 + m;
        const int wbase = m * (XLD / 2);
        if (node < N_NODES) {
            const int my_e = edges[node * DEG + lane];

            float acc8[8];
            #pragma unroll
            for (int r = 0; r < 8; r++) acc8[r] = 0.f;

            #pragma unroll
            for (int q = 0; q < DEG / 2; q++) {
                const int idx = __shfl_sync(0xffffffffu, my_e, 2 * q + half);
                const uint4 w = *reinterpret_cast<const uint4*>(
                    g_fh + idx * (DFEAT / 2) + lL * 4);
                const float2 f0 = __half22float2(*reinterpret_cast<const __half2*>(&w.x));
                const float2 f1 = __half22float2(*reinterpret_cast<const __half2*>(&w.y));
                const float2 f2 = __half22float2(*reinterpret_cast<const __half2*>(&w.z));
                const float2 f3 = __half22float2(*reinterpret_cast<const __half2*>(&w.w));
                acc8[0] += f0.x; acc8[1] += f0.y;
                acc8[2] += f1.x; acc8[3] += f1.y;
                acc8[4] += f2.x; acc8[5] += f2.y;
                acc8[6] += f3.x; acc8[7] += f3.y;
            }
            // fold odd-row partial sums (lanes 16-31) into lanes 0-15
            #pragma unroll
            for (int r = 0; r < 8; r++)
                acc8[r] += __shfl_down_sync(0xffffffffu, acc8[r], 16);

            if (half == 0) {
                // lanes 0-15: scale, split, store AGG cols [8lL..8lL+8)
                const float inv = 1.0f / (float)DEG;
                uint32_t h[4], l[4];
                #pragma unroll
                for (int r = 0; r < 4; r++)
                    f16x2_split(acc8[2 * r] * inv, acc8[2 * r + 1] * inv, h[r], l[r]);
                *reinterpret_cast<uint4*>(xs_hi + wbase + 64 + lL * 4) =
                    make_uint4(h[0], h[1], h[2], h[3]);
                *reinterpret_cast<uint4*>(xs_lo + wbase + 64 + lL * 4) =
                    make_uint4(l[0], l[1], l[2], l[3]);
            } else {
                // lanes 16-31: load fp32 SELF cols [8lL..8lL+8), split, store
                const float4 s0 = *reinterpret_cast<const float4*>(
                    features + (long long)node * DFEAT + lL * 8);
                const float4 s1 = *reinterpret_cast<const float4*>(
                    features + (long long)node * DFEAT + lL * 8 + 4);
                uint32_t h[4], l[4];
                f16x2_split(s0.x, s0.y, h[0], l[0]);
                f16x2_split(s0.z, s0.w, h[1], l[1]);
                f16x2_split(s1.x, s1.y, h[2], l[2]);
                f16x2_split(s1.z, s1.w, h[3], l[3]);
                *reinterpret_cast<uint4*>(xs_hi + wbase + lL * 4) =
                    make_uint4(h[0], h[1], h[2], h[3]);
                *reinterpret_cast<uint4*>(xs_lo + wbase + lL * 4) =
                    make_uint4(l[0], l[1], l[2], l[3]);
            }
        } else {
            const uint4 z = make_uint4(0u, 0u, 0u, 0u);
            const int off = (half == 0) ? 64 : 0;
            *reinterpret_cast<uint4*>(xs_hi + wbase + off + lL * 4) = z;
            *reinterpret_cast<uint4*>(xs_lo + wbase + off + lL * 4) = z;
        }
    }
    __syncthreads();

    // ---------------- Phase 2: fp16x2 GEMM, B direct from L2 ---------------
    // 8 warps, each owns M=32 x 32 N-cols; mt SEQUENTIAL to fit 64 regs.
    const int g  = lane >> 2;
    const int t  = lane & 3;
    const int n_base = wid * 32;

    float acc[2][4][4];
    #pragma unroll
    for (int mt = 0; mt < 2; mt++)
        #pragma unroll
        for (int nt = 0; nt < 4; nt++)
            #pragma unroll
            for (int r = 0; r < 4; r++)
                acc[mt][nt][r] = 0.f;

    // nblk = wid*4 + nt
    const uint2* wbase_p = g_wfrag + (wid * 4) * 32 + lane;

    #pragma unroll 1
    for (int ksg = 0; ksg < 16; ksg++) {
        uint2 bw[4];
        #pragma unroll
        for (int q = 0; q < 4; q++)
            bw[q] = wbase_p[(ksg * 32 + q) * 32];

        #pragma unroll
        for (int mt = 0; mt < 2; mt++) {
            const int r0 = mt * 16 + g;
            const int i00 = r0 * (XLD / 2) + ksg * 8 + t;
            const int i01 = (r0 + 8) * (XLD / 2) + ksg * 8 + t;
            uint32_t ah[4], al[4];
            ah[0] = xs_hi[i00];     al[0] = xs_lo[i00];
            ah[1] = xs_hi[i01];     al[1] = xs_lo[i01];
            ah[2] = xs_hi[i00 + 4]; al[2] = xs_lo[i00 + 4];
            ah[3] = xs_hi[i01 + 4]; al[3] = xs_lo[i01 + 4];

            #pragma unroll
            for (int nt = 0; nt < 4; nt++) {
                mma_f16(acc[mt][nt], ah, bw[nt].x, bw[nt].y);  // Ah*W
                mma_f16(acc[mt][nt], al, bw[nt].x, bw[nt].y);  // Al*W
            }
        }
    }

    // ---------------- Phase 3: ReLU + store from registers -----------------
    #pragma unroll
    for (int mt = 0; mt < 2; mt++) {
        const int r0 = node0 + mt * 16 + g;
        #pragma unroll
        for (int nt = 0; nt < 4; nt++) {
            const int c0 = n_base + nt * 8 + t * 2;
            if (r0 < N_NODES) {
                float2 v0 = make_float2(fmaxf(acc[mt][nt][0], 0.f),
                                        fmaxf(acc[mt][nt][1], 0.f));
                *reinterpret_cast<float2*>(out + (long long)r0 * DOUT + c0) = v0;
            }
            if (r0 + 8 < N_NODES) {
                float2 v1 = make_float2(fmaxf(acc[mt][nt][2], 0.f),
                                        fmaxf(acc[mt][nt][3], 0.f));
                *reinterpret_cast<float2*>(out + (long long)(r0 + 8) * DOUT + c0) = v1;
            }
        }
    }
}

extern "C" void kernel_launch(void* const* d_in, const int* in_sizes, int n_in,
                              void* d_out, int out_size)
{
    const float* features = (const float*)d_in[0];
    const int*   edges    = (const int*)d_in[1];
    const float* kernel   = (const float*)d_in[2];
    float*       out      = (float*)d_out;
    (void)in_sizes; (void)n_in; (void)out_size;

    static bool attr_set = false;
    if (!attr_set) {
        cudaFuncSetAttribute(sage_fused_kernel,
                             cudaFuncAttributeMaxDynamicSharedMemorySize, SMEM_BYTES);
        attr_set = true;
    }

    // 800000 uint4 elems / 256 = 3125 blocks
    f2h_kernel<<<(N_NODES * DFEAT / 8) / 256, 256>>>(features);
    wsplit_kernel<<<64, 256>>>(kernel);
    const int grid = (N_NODES + BM - 1) / BM;   // 1563
    sage_fused_kernel<<<grid, 256, SMEM_BYTES>>>(features, edges, out);
}